// round 9
// baseline (speedup 1.0000x reference)
// SSMDiagScan_84731114816205 — gated diagonal SSM
//   y = c * scan(aa, b*u_g) + d_eff * u_g,  u_g = u * sigmoid(u @ W^T + gb)
// K0: fp32->fp16 pre-convert of W only (8 MB)
// K1: fp16 mma.sync m16n8k16 (fp32 accum) GEMM at the legacy-tensor floor.
//     A loaded as fp32 (cp.async, pitch-72 smem) and converted to fp16
//     fragments in registers (hides the old conv-U kernel under the
//     tensor-bound mainloop). B via SW128 fp16 + ldmatrix. Fused sigmoid/u_g
//     epilogue (fp16 u_g out) + deterministic colsum partials.
// K2: rank-4 reduction (8 blocks)   K3: per-channel scan, single wave

#include <cuda_runtime.h>
#include <cuda_fp16.h>
#include <cstdint>

static constexpr int Bdim = 8;
static constexpr int Tdim = 2048;
static constexpr int Ddim = 2048;
static constexpr int Mdim = Bdim * Tdim;          // 16384
static constexpr int BM = 128, BN = 128, BK = 64;
static constexpr int KTILES = Ddim / BK;          // 32
static constexpr int MTILES = Mdim / BM;          // 128
static constexpr int NTILES = Ddim / BN;          // 16
static constexpr int APITCH = 72;                 // fp32 A row pitch (floats)
static constexpr int A32_FLOATS = BM * APITCH;    // 9216 floats = 36864 B
static constexpr int B_TILE_BYTES = BN * BK * 2;  // 16384
static constexpr int DYN_BYTES = 2 * A32_FLOATS * 4 + 2 * B_TILE_BYTES; // 106496

// Scratch (device globals: allocation-free rule)
__device__ __half g_ugh[(size_t)Mdim * Ddim];         // 64 MB (u_g fp16)
__device__ __half g_wh[(size_t)Ddim * Ddim];          // 8 MB
__device__ float  g_partials[(size_t)MTILES * Ddim];
__device__ float  g_r[Bdim * 4];

// ---------------- helpers ----------------
__device__ __forceinline__ uint32_t cvta_shared(const void* p) {
    uint32_t a;
    asm("{ .reg .u64 t; cvta.to.shared.u64 t, %1; cvt.u32.u64 %0, t; }"
        : "=r"(a) : "l"(p));
    return a;
}
__device__ __forceinline__ void cp_async16(uint32_t saddr, const void* gaddr) {
    asm volatile("cp.async.cg.shared.global [%0], [%1], 16;"
                 :: "r"(saddr), "l"(gaddr) : "memory");
}
__device__ __forceinline__ void cp_commit() {
    asm volatile("cp.async.commit_group;" ::: "memory");
}
template <int N>
__device__ __forceinline__ void cp_wait() {
    asm volatile("cp.async.wait_group %0;" :: "n"(N) : "memory");
}
__device__ __forceinline__ uint32_t sw128(uint32_t off) {
    return off ^ ((off >> 3) & 0x70);
}
__device__ __forceinline__ void ldsm_x4(uint32_t* r, uint32_t addr) {
    asm volatile("ldmatrix.sync.aligned.m8n8.x4.shared.b16 {%0,%1,%2,%3}, [%4];"
                 : "=r"(r[0]), "=r"(r[1]), "=r"(r[2]), "=r"(r[3]) : "r"(addr));
}
__device__ __forceinline__ uint32_t packh2(float2 f) {
    uint32_t r;
    asm("cvt.rn.f16x2.f32 %0, %1, %2;" : "=r"(r) : "f"(f.y), "f"(f.x));
    return r;
}
__device__ __forceinline__ void mma_f16(float& d0, float& d1, float& d2, float& d3,
                                        uint32_t a0, uint32_t a1, uint32_t a2,
                                        uint32_t a3, uint32_t b0, uint32_t b1) {
    asm volatile(
        "mma.sync.aligned.m16n8k16.row.col.f32.f16.f16.f32 "
        "{%0,%1,%2,%3}, {%4,%5,%6,%7}, {%8,%9}, {%0,%1,%2,%3};"
        : "+f"(d0), "+f"(d1), "+f"(d2), "+f"(d3)
        : "r"(a0), "r"(a1), "r"(a2), "r"(a3), "r"(b0), "r"(b1));
}

// ============ Kernel 0: fp32 -> fp16 convert (W only) ============
__global__ __launch_bounds__(256)
void conv_half(const float* __restrict__ src, __half* __restrict__ dst) {
    const size_t i = (size_t)blockIdx.x * 256 + threadIdx.x;
    float4 v = ((const float4*)src)[i];
    ((__half2*)dst)[2 * i] = __floats2half2_rn(v.x, v.y);
    ((__half2*)dst)[2 * i + 1] = __floats2half2_rn(v.z, v.w);
}

// ======= Kernel 1: fp16 mma.sync GEMM (fp32 accum) + gate epilogue =======
__global__ __launch_bounds__(256, 2)
void gemm_gate_mma(const float* __restrict__ U,
                   const float* __restrict__ gb) {
    extern __shared__ __align__(16) float sm[];
    __shared__ float s_gb[BN];
    __shared__ float s_red[2][BN];

    const int tid = threadIdx.x;
    const int wid = tid >> 5;
    const int lane = tid & 31;
    const int g = lane >> 2;        // octet row (0..7)
    const int t = lane & 3;         // thread-in-group (0..3)
    const int grp = lane >> 3;      // ldmatrix address group (0..3)
    const int lrow = lane & 7;
    const int warp_m = wid >> 2;    // 0..1  (64-row slabs)
    const int warp_n = wid & 3;     // 0..3  (32-col slabs)
    const int n0 = blockIdx.x * BN;
    const int m0 = blockIdx.y * BM;
    const uint32_t smem_base = cvta_shared(sm);
    const uint32_t b_base = smem_base + 2u * A32_FLOATS * 4;

    const int rowoff_b = ((grp >> 1) << 3) + lrow;
    const int koff_b = (grp & 1) << 4;

    for (int i = tid; i < BN; i += 256) s_gb[i] = gb[n0 + i];

    float acc[4][4][4];             // [m16 tile][n8 tile][c0..c3]
#pragma unroll
    for (int i = 0; i < 4; i++)
#pragma unroll
        for (int j = 0; j < 4; j++)
#pragma unroll
            for (int r = 0; r < 4; r++) acc[i][j][r] = 0.f;

    // A: fp32 tile, 128 rows x 64 floats (256B), pitch 72 floats (288B)
    // B: fp16 tile from g_wh, SW128 layout for ldmatrix
    auto load_tile = [&](int kt, int s) {
        const uint32_t ab = smem_base + (uint32_t)(s * A32_FLOATS) * 4;
        const uint32_t bb = b_base + (uint32_t)s * B_TILE_BYTES;
        const float* gA = U + (size_t)m0 * Ddim + kt * BK;
        const __half* gB = g_wh + (size_t)n0 * Ddim + kt * BK;
#pragma unroll
        for (int i = 0; i < 8; i++) {                // 2048 float4 segs
            const int id = tid + i * 256;
            const int row = id >> 4, c = id & 15;
            cp_async16(ab + (uint32_t)(row * 288 + c * 16),
                       gA + (size_t)row * Ddim + c * 4);
        }
#pragma unroll
        for (int i = 0; i < 4; i++) {                // 1024 16B segs
            const int id = tid + i * 256;
            const int row = id >> 3, c = id & 7;
            cp_async16(bb + sw128((uint32_t)(row * 128 + c * 16)),
                       gB + (size_t)row * Ddim + c * 8);
        }
    };

    auto compute_tile = [&](int st) {
        const float* Af = sm + st * A32_FLOATS;
        const uint32_t bb = b_base + (uint32_t)st * B_TILE_BYTES;
#pragma unroll
        for (int s = 0; s < BK / 16; s++) {          // 4 k-steps of 16
            uint32_t a[4][4], b[2][4];
#pragma unroll
            for (int i = 0; i < 4; i++) {
                const int r0 = warp_m * 64 + i * 16 + g;
                const int kc = s * 16 + 2 * t;
                const float2 f0 = *(const float2*)&Af[r0 * APITCH + kc];
                const float2 f1 = *(const float2*)&Af[(r0 + 8) * APITCH + kc];
                const float2 f2 = *(const float2*)&Af[r0 * APITCH + kc + 8];
                const float2 f3 = *(const float2*)&Af[(r0 + 8) * APITCH + kc + 8];
                a[i][0] = packh2(f0);
                a[i][1] = packh2(f1);
                a[i][2] = packh2(f2);
                a[i][3] = packh2(f3);
            }
#pragma unroll
            for (int jj = 0; jj < 2; jj++) {
                const int row = warp_n * 32 + jj * 16 + rowoff_b;
                ldsm_x4(b[jj], bb + sw128((uint32_t)(row * 128 + s * 32 + koff_b)));
            }
#pragma unroll
            for (int i = 0; i < 4; i++)
#pragma unroll
                for (int j = 0; j < 4; j++)
                    mma_f16(acc[i][j][0], acc[i][j][1], acc[i][j][2], acc[i][j][3],
                            a[i][0], a[i][1], a[i][2], a[i][3],
                            b[j >> 1][(j & 1) * 2 + 0], b[j >> 1][(j & 1) * 2 + 1]);
        }
    };

    // ---- 2-stage pipeline ----
    load_tile(0, 0);
    cp_commit();
#pragma unroll 1
    for (int kt = 0; kt < KTILES; ++kt) {
        if (kt < KTILES - 1) {
            load_tile(kt + 1, (kt + 1) & 1);
            cp_commit();
            cp_wait<1>();
        } else {
            cp_wait<0>();
        }
        __syncthreads();
        compute_tile(kt & 1);
        __syncthreads();
    }

    // ---- epilogue: sigmoid gate, u_g (fp16 out), colsum partials ----
    float csum[4][2];
#pragma unroll
    for (int j = 0; j < 4; j++) { csum[j][0] = 0.f; csum[j][1] = 0.f; }

#pragma unroll
    for (int j = 0; j < 4; j++) {
        const int col = warp_n * 32 + j * 8 + 2 * t;
        const float gb0 = s_gb[col];
        const float gb1 = s_gb[col + 1];
#pragma unroll
        for (int i = 0; i < 4; i++) {
#pragma unroll
            for (int h = 0; h < 2; h++) {
                const int row = warp_m * 64 + i * 16 + h * 8 + g;
                const size_t off = (size_t)(m0 + row) * Ddim + n0 + col;
                const float2 uu = *(const float2*)(U + off);
                const float l0 = acc[i][j][h * 2 + 0] + gb0;
                const float l1 = acc[i][j][h * 2 + 1] + gb1;
                const float ug0 = uu.x * (1.f / (1.f + __expf(-l0)));
                const float ug1 = uu.y * (1.f / (1.f + __expf(-l1)));
                *(__half2*)(g_ugh + off) = __floats2half2_rn(ug0, ug1);
                csum[j][0] += ug0;
                csum[j][1] += ug1;
            }
        }
    }
#pragma unroll
    for (int j = 0; j < 4; j++) {
#pragma unroll
        for (int mask = 16; mask >= 4; mask >>= 1) {
            csum[j][0] += __shfl_xor_sync(0xffffffffu, csum[j][0], mask);
            csum[j][1] += __shfl_xor_sync(0xffffffffu, csum[j][1], mask);
        }
    }
    if (g == 0) {
#pragma unroll
        for (int j = 0; j < 4; j++) {
            s_red[warp_m][warp_n * 32 + j * 8 + 2 * t] = csum[j][0];
            s_red[warp_m][warp_n * 32 + j * 8 + 2 * t + 1] = csum[j][1];
        }
    }
    __syncthreads();
    if (tid < BN)
        g_partials[(size_t)blockIdx.y * Ddim + n0 + tid] =
            s_red[0][tid] + s_red[1][tid];
}

// ==== Kernel 2: r[b][0..3] = sum_e mean_ug[b][e] * dlru[e][0..3] (grid 8) ===
__global__ __launch_bounds__(256)
void rvec_kernel(const float* __restrict__ dlru) {   // [D, 4]
    const int b = blockIdx.x;        // 0..7
    const int tid = threadIdx.x;     // 256
    __shared__ float red[4][256];
    float a0 = 0.f, a1 = 0.f, a2 = 0.f, a3 = 0.f;
    for (int e = tid; e < Ddim; e += 256) {
        float s = 0.f;
#pragma unroll
        for (int i = 0; i < 16; i++)
            s += g_partials[(size_t)(b * 16 + i) * Ddim + e];
        const float mean = s * (1.0f / Tdim);
        const float4 w = ((const float4*)dlru)[e];
        a0 += mean * w.x; a1 += mean * w.y; a2 += mean * w.z; a3 += mean * w.w;
    }
    red[0][tid] = a0; red[1][tid] = a1; red[2][tid] = a2; red[3][tid] = a3;
    __syncthreads();
    for (int off = 128; off > 0; off >>= 1) {
        if (tid < off) {
            red[0][tid] += red[0][tid + off];
            red[1][tid] += red[1][tid + off];
            red[2][tid] += red[2][tid + off];
            red[3][tid] += red[3][tid + off];
        }
        __syncthreads();
    }
    if (tid < 4) g_r[b * 4 + tid] = red[tid][0];
}

// ==== Kernel 3: per-channel scan with inline d_eff (single wave) ===========
__global__ __launch_bounds__(128)
void scan_kernel(const float* __restrict__ av,
                 const float* __restrict__ bv,
                 const float* __restrict__ cv,
                 const float* __restrict__ dvec,
                 const float* __restrict__ dlrv,   // [4, D]
                 float* __restrict__ Y) {
    const int ch = blockIdx.x * 128 + threadIdx.x;  // 0 .. B*D-1
    const int b = ch >> 11;
    const int dd = ch & (Ddim - 1);
    const float aa = tanhf(av[dd]);
    const float bb = bv[dd];
    const float cc = cv[dd];
    const float de = dvec[dd] +
        0.25f * (g_r[b * 4 + 0] * dlrv[dd] +
                 g_r[b * 4 + 1] * dlrv[Ddim + dd] +
                 g_r[b * 4 + 2] * dlrv[2 * Ddim + dd] +
                 g_r[b * 4 + 3] * dlrv[3 * Ddim + dd]);
    const __half* p = g_ugh + (size_t)b * Tdim * Ddim + dd;
    float* q = Y + (size_t)b * Tdim * Ddim + dd;
    float s = 0.f;
    for (int t0 = 0; t0 < Tdim; t0 += 32) {
        __half x[32];
#pragma unroll
        for (int j = 0; j < 32; j++) x[j] = p[(size_t)(t0 + j) * Ddim];
#pragma unroll
        for (int j = 0; j < 32; j++) {
            const float xf = __half2float(x[j]);
            s = fmaf(aa, s, bb * xf);
            q[(size_t)(t0 + j) * Ddim] = fmaf(cc, s, de * xf);
        }
    }
}

extern "C" void kernel_launch(void* const* d_in, const int* in_sizes, int n_in,
                              void* d_out, int out_size) {
    const float* U    = (const float*)d_in[0];  // [B,T,D]
    const float* av   = (const float*)d_in[1];  // [D]
    const float* bv   = (const float*)d_in[2];  // [D]
    const float* cv   = (const float*)d_in[3];  // [D]
    const float* dv   = (const float*)d_in[4];  // [D]
    const float* gw   = (const float*)d_in[5];  // [D,D]
    const float* gbp  = (const float*)d_in[6];  // [D]
    const float* dlru = (const float*)d_in[7];  // [D,4]
    const float* dlrv = (const float*)d_in[8];  // [4,D]
    float* Y = (float*)d_out;

    __half* wh_p; cudaGetSymbolAddress((void**)&wh_p, g_wh);

    conv_half<<<((size_t)Ddim * Ddim / 4) / 256, 256>>>(gw, wh_p);

    cudaFuncSetAttribute(gemm_gate_mma,
                         cudaFuncAttributeMaxDynamicSharedMemorySize, DYN_BYTES);
    gemm_gate_mma<<<dim3(NTILES, MTILES), 256, DYN_BYTES>>>(U, gbp);
    rvec_kernel<<<Bdim, 256>>>(dlru);
    scan_kernel<<<(Bdim * Ddim) / 128, 128>>>(av, bv, cv, dv, dlrv, Y);
}

// round 10
// speedup vs baseline: 1.3184x; 1.3184x over previous
// SSMDiagScan_84731114816205 — gated diagonal SSM
//   y = c * scan(aa, b*u_g) + d_eff * u_g,  u_g = u * sigmoid(u @ W^T + gb)
// K0: fp32->fp16 pre-convert of U and W
// K1: fp16 mma.sync m16n8k16 (fp32 accum) GEMM, 128x128x64 tiles, 3-stage
//     cp.async, ldmatrix, fused sigmoid/u_g epilogue (fp16 u_g out) +
//     deterministic colsum partials.  (legacy-tensor-pipe floor ~390us)
// K2: rank-4 reduction (8 blocks)
// K3: 3-phase chunked parallel scan (C=16 chunks of L=128): carries ->
//     per-channel prefix combine -> replay+output.  16x the threads of the
//     serial scan; bandwidth-bound instead of latency-bound.

#include <cuda_runtime.h>
#include <cuda_fp16.h>
#include <cstdint>

static constexpr int Bdim = 8;
static constexpr int Tdim = 2048;
static constexpr int Ddim = 2048;
static constexpr int Mdim = Bdim * Tdim;          // 16384
static constexpr int BM = 128, BN = 128, BK = 64;
static constexpr int KTILES = Ddim / BK;          // 32
static constexpr int MTILES = Mdim / BM;          // 128
static constexpr int NTILES = Ddim / BN;          // 16
static constexpr int STAGES = 3;
static constexpr int A_TILE_BYTES = BM * BK * 2;  // 16384
static constexpr int STAGE_BYTES = 2 * A_TILE_BYTES;      // 32768 (A+B)
static constexpr int DYN_BYTES = STAGES * STAGE_BYTES;    // 98304

static constexpr int CCH = 16;                    // scan chunks per channel
static constexpr int LCH = Tdim / CCH;            // 128 steps per chunk
static constexpr int NCH = Bdim * Ddim;           // 16384 channels

// Scratch (device globals: allocation-free rule)
__device__ __half g_ugh[(size_t)Mdim * Ddim];         // 64 MB (u_g fp16)
__device__ __half g_uh[(size_t)Mdim * Ddim];          // 64 MB
__device__ __half g_wh[(size_t)Ddim * Ddim];          // 8 MB
__device__ float  g_partials[(size_t)MTILES * Ddim];
__device__ float  g_r[Bdim * 4];
__device__ float  g_carry[NCH * CCH];                 // 1 MB
__device__ float  g_state[NCH * CCH];                 // 1 MB

// ---------------- helpers ----------------
__device__ __forceinline__ uint32_t cvta_shared(const void* p) {
    uint32_t a;
    asm("{ .reg .u64 t; cvta.to.shared.u64 t, %1; cvt.u32.u64 %0, t; }"
        : "=r"(a) : "l"(p));
    return a;
}
__device__ __forceinline__ void cp_async16(uint32_t saddr, const void* gaddr) {
    asm volatile("cp.async.cg.shared.global [%0], [%1], 16;"
                 :: "r"(saddr), "l"(gaddr) : "memory");
}
__device__ __forceinline__ void cp_commit() {
    asm volatile("cp.async.commit_group;" ::: "memory");
}
template <int N>
__device__ __forceinline__ void cp_wait() {
    asm volatile("cp.async.wait_group %0;" :: "n"(N) : "memory");
}
__device__ __forceinline__ uint32_t sw128(uint32_t off) {
    return off ^ ((off >> 3) & 0x70);
}
__device__ __forceinline__ void ldsm_x4(uint32_t* r, uint32_t addr) {
    asm volatile("ldmatrix.sync.aligned.m8n8.x4.shared.b16 {%0,%1,%2,%3}, [%4];"
                 : "=r"(r[0]), "=r"(r[1]), "=r"(r[2]), "=r"(r[3]) : "r"(addr));
}
__device__ __forceinline__ void mma_f16(float& d0, float& d1, float& d2, float& d3,
                                        uint32_t a0, uint32_t a1, uint32_t a2,
                                        uint32_t a3, uint32_t b0, uint32_t b1) {
    asm volatile(
        "mma.sync.aligned.m16n8k16.row.col.f32.f16.f16.f32 "
        "{%0,%1,%2,%3}, {%4,%5,%6,%7}, {%8,%9}, {%0,%1,%2,%3};"
        : "+f"(d0), "+f"(d1), "+f"(d2), "+f"(d3)
        : "r"(a0), "r"(a1), "r"(a2), "r"(a3), "r"(b0), "r"(b1));
}

// ============ Kernel 0: fp32 -> fp16 convert (vectorized) ============
__global__ __launch_bounds__(256)
void conv_half(const float* __restrict__ src, __half* __restrict__ dst) {
    const size_t i = (size_t)blockIdx.x * 256 + threadIdx.x;
    float4 v = ((const float4*)src)[i];
    ((__half2*)dst)[2 * i] = __floats2half2_rn(v.x, v.y);
    ((__half2*)dst)[2 * i + 1] = __floats2half2_rn(v.z, v.w);
}

// ======= Kernel 1: fp16 mma.sync GEMM (fp32 accum) + gate epilogue =======
__global__ __launch_bounds__(256, 2)
void gemm_gate_mma(const float* __restrict__ gb) {
    extern __shared__ __align__(128) char sm[];
    __shared__ float s_gb[BN];
    __shared__ float s_red[2][BN];

    const int tid = threadIdx.x;
    const int wid = tid >> 5;
    const int lane = tid & 31;
    const int g = lane >> 2;        // octet row (0..7)
    const int t = lane & 3;         // thread-in-group (0..3)
    const int grp = lane >> 3;      // ldmatrix address group (0..3)
    const int lrow = lane & 7;
    const int warp_m = wid >> 2;    // 0..1  (64-row slabs)
    const int warp_n = wid & 3;     // 0..3  (32-col slabs)
    const int n0 = blockIdx.x * BN;
    const int m0 = blockIdx.y * BM;
    const uint32_t smem_base = cvta_shared(sm);

    const int rowoff_a = ((grp & 1) << 3) + lrow;
    const int koff_a = (grp >> 1) << 4;
    const int rowoff_b = ((grp >> 1) << 3) + lrow;
    const int koff_b = (grp & 1) << 4;

    for (int i = tid; i < BN; i += 256) s_gb[i] = gb[n0 + i];

    float acc[4][4][4];             // [m16 tile][n8 tile][c0..c3]
#pragma unroll
    for (int i = 0; i < 4; i++)
#pragma unroll
        for (int j = 0; j < 4; j++)
#pragma unroll
            for (int r = 0; r < 4; r++) acc[i][j][r] = 0.f;

    auto load_tile = [&](int kt, int s) {
        const uint32_t ab = smem_base + (uint32_t)s * STAGE_BYTES;
        const uint32_t bb = ab + A_TILE_BYTES;
        const __half* gA = g_uh + (size_t)m0 * Ddim + kt * BK;
        const __half* gB = g_wh + (size_t)n0 * Ddim + kt * BK;
#pragma unroll
        for (int i = 0; i < 4; i++) {
            const int id = tid + i * 256;
            const int row = id >> 3, c = id & 7;
            cp_async16(ab + sw128((uint32_t)(row * 128 + c * 16)),
                       gA + (size_t)row * Ddim + c * 8);
        }
#pragma unroll
        for (int i = 0; i < 4; i++) {
            const int id = tid + i * 256;
            const int row = id >> 3, c = id & 7;
            cp_async16(bb + sw128((uint32_t)(row * 128 + c * 16)),
                       gB + (size_t)row * Ddim + c * 8);
        }
    };

    auto compute_tile = [&](int st) {
        const uint32_t ab = smem_base + (uint32_t)st * STAGE_BYTES;
        const uint32_t bb = ab + A_TILE_BYTES;
#pragma unroll
        for (int s = 0; s < BK / 16; s++) {          // 4 k-steps of 16
            uint32_t a[4][4], b[2][4];
#pragma unroll
            for (int i = 0; i < 4; i++) {
                const int row = warp_m * 64 + i * 16 + rowoff_a;
                ldsm_x4(a[i], ab + sw128((uint32_t)(row * 128 + s * 32 + koff_a)));
            }
#pragma unroll
            for (int jj = 0; jj < 2; jj++) {
                const int row = warp_n * 32 + jj * 16 + rowoff_b;
                ldsm_x4(b[jj], bb + sw128((uint32_t)(row * 128 + s * 32 + koff_b)));
            }
#pragma unroll
            for (int i = 0; i < 4; i++)
#pragma unroll
                for (int j = 0; j < 4; j++)
                    mma_f16(acc[i][j][0], acc[i][j][1], acc[i][j][2], acc[i][j][3],
                            a[i][0], a[i][1], a[i][2], a[i][3],
                            b[j >> 1][(j & 1) * 2 + 0], b[j >> 1][(j & 1) * 2 + 1]);
        }
    };

    // ---- 3-stage pipeline, one syncthreads per iteration ----
    load_tile(0, 0);
    cp_commit();
    load_tile(1, 1);
    cp_commit();
#pragma unroll 1
    for (int kt = 0; kt < KTILES; ++kt) {
        cp_wait<1>();                      // stage kt resident
        __syncthreads();                   // all warps done with stage kt-1
        if (kt + 2 < KTILES) load_tile(kt + 2, (kt + 2) % STAGES);
        cp_commit();
        compute_tile(kt % STAGES);
    }

    // ---- epilogue: sigmoid gate, u_g (fp16 out), colsum partials ----
    float csum[4][2];
#pragma unroll
    for (int j = 0; j < 4; j++) { csum[j][0] = 0.f; csum[j][1] = 0.f; }

#pragma unroll
    for (int j = 0; j < 4; j++) {
        const int col = warp_n * 32 + j * 8 + 2 * t;
        const float gb0 = s_gb[col];
        const float gb1 = s_gb[col + 1];
#pragma unroll
        for (int i = 0; i < 4; i++) {
#pragma unroll
            for (int h = 0; h < 2; h++) {
                const int row = warp_m * 64 + i * 16 + h * 8 + g;
                const size_t off = (size_t)(m0 + row) * Ddim + n0 + col;
                const __half2 uu = *(const __half2*)(g_uh + off);
                const float l0 = acc[i][j][h * 2 + 0] + gb0;
                const float l1 = acc[i][j][h * 2 + 1] + gb1;
                const float ug0 = __half2float(uu.x) * (1.f / (1.f + __expf(-l0)));
                const float ug1 = __half2float(uu.y) * (1.f / (1.f + __expf(-l1)));
                *(__half2*)(g_ugh + off) = __floats2half2_rn(ug0, ug1);
                csum[j][0] += ug0;
                csum[j][1] += ug1;
            }
        }
    }
#pragma unroll
    for (int j = 0; j < 4; j++) {
#pragma unroll
        for (int mask = 16; mask >= 4; mask >>= 1) {
            csum[j][0] += __shfl_xor_sync(0xffffffffu, csum[j][0], mask);
            csum[j][1] += __shfl_xor_sync(0xffffffffu, csum[j][1], mask);
        }
    }
    if (g == 0) {
#pragma unroll
        for (int j = 0; j < 4; j++) {
            s_red[warp_m][warp_n * 32 + j * 8 + 2 * t] = csum[j][0];
            s_red[warp_m][warp_n * 32 + j * 8 + 2 * t + 1] = csum[j][1];
        }
    }
    __syncthreads();
    if (tid < BN)
        g_partials[(size_t)blockIdx.y * Ddim + n0 + tid] =
            s_red[0][tid] + s_red[1][tid];
}

// ==== Kernel 2: r[b][0..3] = sum_e mean_ug[b][e] * dlru[e][0..3] (grid 8) ===
__global__ __launch_bounds__(256)
void rvec_kernel(const float* __restrict__ dlru) {   // [D, 4]
    const int b = blockIdx.x;        // 0..7
    const int tid = threadIdx.x;     // 256
    __shared__ float red[4][256];
    float a0 = 0.f, a1 = 0.f, a2 = 0.f, a3 = 0.f;
    for (int e = tid; e < Ddim; e += 256) {
        float s = 0.f;
#pragma unroll
        for (int i = 0; i < 16; i++)
            s += g_partials[(size_t)(b * 16 + i) * Ddim + e];
        const float mean = s * (1.0f / Tdim);
        const float4 w = ((const float4*)dlru)[e];
        a0 += mean * w.x; a1 += mean * w.y; a2 += mean * w.z; a3 += mean * w.w;
    }
    red[0][tid] = a0; red[1][tid] = a1; red[2][tid] = a2; red[3][tid] = a3;
    __syncthreads();
    for (int off = 128; off > 0; off >>= 1) {
        if (tid < off) {
            red[0][tid] += red[0][tid + off];
            red[1][tid] += red[1][tid + off];
            red[2][tid] += red[2][tid + off];
            red[3][tid] += red[3][tid + off];
        }
        __syncthreads();
    }
    if (tid < 4) g_r[b * 4 + tid] = red[tid][0];
}

// ==== Kernel 3a: per-(channel,chunk) zero-init carry ======================
__global__ __launch_bounds__(256)
void scan_p1(const float* __restrict__ av, const float* __restrict__ bv) {
    const int gidx = blockIdx.x * 256 + threadIdx.x;   // 0 .. NCH*CCH-1
    const int dd = gidx & (Ddim - 1);
    const int rest = gidx >> 11;                        // b*CCH + chunk
    const float aa = tanhf(av[dd]);
    const float bb = bv[dd];
    const __half* p = g_ugh + (size_t)rest * LCH * Ddim + dd;
    float s = 0.f;
#pragma unroll 1
    for (int t0 = 0; t0 < LCH; t0 += 8) {
        __half x[8];
#pragma unroll
        for (int j = 0; j < 8; j++) x[j] = p[(size_t)(t0 + j) * Ddim];
#pragma unroll
        for (int j = 0; j < 8; j++)
            s = fmaf(aa, s, bb * __half2float(x[j]));
    }
    g_carry[gidx] = s;
}

// ==== Kernel 3b: per-channel prefix combine (aa^L exact squarings) ========
__global__ __launch_bounds__(256)
void scan_p2(const float* __restrict__ av) {
    const int q = blockIdx.x * 256 + threadIdx.x;       // 0 .. NCH-1
    const int dd = q & (Ddim - 1);
    const int b = q >> 11;
    const float aa = tanhf(av[dd]);
    float aL = aa;                                      // aa^128 = 7 squarings
#pragma unroll
    for (int i = 0; i < 7; i++) aL *= aL;
    float s = 0.f;
#pragma unroll
    for (int j = 0; j < CCH; j++) {
        const int idx = (b * CCH + j) * Ddim + dd;
        g_state[idx] = s;                               // state entering chunk j
        s = fmaf(aL, s, g_carry[idx]);
    }
}

// ==== Kernel 3c: replay chunks with true init state, write y ==============
__global__ __launch_bounds__(256)
void scan_p3(const float* __restrict__ av,
             const float* __restrict__ bv,
             const float* __restrict__ cv,
             const float* __restrict__ dvec,
             const float* __restrict__ dlrv,   // [4, D]
             float* __restrict__ Y) {
    const int gidx = blockIdx.x * 256 + threadIdx.x;   // 0 .. NCH*CCH-1
    const int dd = gidx & (Ddim - 1);
    const int rest = gidx >> 11;                        // b*CCH + chunk
    const int b = rest >> 4;
    const float aa = tanhf(av[dd]);
    const float bb = bv[dd];
    const float cc = cv[dd];
    const float de = dvec[dd] +
        0.25f * (g_r[b * 4 + 0] * dlrv[dd] +
                 g_r[b * 4 + 1] * dlrv[Ddim + dd] +
                 g_r[b * 4 + 2] * dlrv[2 * Ddim + dd] +
                 g_r[b * 4 + 3] * dlrv[3 * Ddim + dd]);
    const __half* p = g_ugh + (size_t)rest * LCH * Ddim + dd;
    float* q = Y + (size_t)rest * LCH * Ddim + dd;
    float s = g_state[gidx];
#pragma unroll 1
    for (int t0 = 0; t0 < LCH; t0 += 8) {
        __half x[8];
#pragma unroll
        for (int j = 0; j < 8; j++) x[j] = p[(size_t)(t0 + j) * Ddim];
#pragma unroll
        for (int j = 0; j < 8; j++) {
            const float xf = __half2float(x[j]);
            s = fmaf(aa, s, bb * xf);
            q[(size_t)(t0 + j) * Ddim] = fmaf(cc, s, de * xf);
        }
    }
}

extern "C" void kernel_launch(void* const* d_in, const int* in_sizes, int n_in,
                              void* d_out, int out_size) {
    const float* U    = (const float*)d_in[0];  // [B,T,D]
    const float* av   = (const float*)d_in[1];  // [D]
    const float* bv   = (const float*)d_in[2];  // [D]
    const float* cv   = (const float*)d_in[3];  // [D]
    const float* dv   = (const float*)d_in[4];  // [D]
    const float* gw   = (const float*)d_in[5];  // [D,D]
    const float* gbp  = (const float*)d_in[6];  // [D]
    const float* dlru = (const float*)d_in[7];  // [D,4]
    const float* dlrv = (const float*)d_in[8];  // [4,D]
    float* Y = (float*)d_out;

    __half* uh_p; cudaGetSymbolAddress((void**)&uh_p, g_uh);
    __half* wh_p; cudaGetSymbolAddress((void**)&wh_p, g_wh);

    conv_half<<<(Mdim * (size_t)Ddim / 4) / 256, 256>>>(U, uh_p);
    conv_half<<<((size_t)Ddim * Ddim / 4) / 256, 256>>>(gw, wh_p);

    cudaFuncSetAttribute(gemm_gate_mma,
                         cudaFuncAttributeMaxDynamicSharedMemorySize, DYN_BYTES);
    gemm_gate_mma<<<dim3(NTILES, MTILES), 256, DYN_BYTES>>>(gbp);
    rvec_kernel<<<Bdim, 256>>>(dlru);
    scan_p1<<<(NCH * CCH) / 256, 256>>>(av, bv);
    scan_p2<<<NCH / 256, 256>>>(av);
    scan_p3<<<(NCH * CCH) / 256, 256>>>(av, bv, cv, dv, dlrv, Y);
}

// round 11
// speedup vs baseline: 1.3692x; 1.0385x over previous
// SSMDiagScan_84731114816205 — gated diagonal SSM
//   y = c * scan(aa, b*u_g) + d_eff * u_g,  u_g = u * sigmoid(u @ W^T + gb)
// K0: fp32->fp16 pre-convert of U and W
// K1: fp16 mma.sync m16n8k16 GEMM (legacy-tensor floor ~390us), fused epilogue:
//     sigmoid gate, fp16 u_g, colsum partials, AND per-(chunk,channel) scan
//     carries (Horner, ratio aa^8) — scan phase 1 lives on K1's idle pipes.
// K2: rank-4 partial reduction (64 blocks)
// K3: p2 per-channel carry combine -> p3 chunk replay + output (+inline d_eff)

#include <cuda_runtime.h>
#include <cuda_fp16.h>
#include <cstdint>

static constexpr int Bdim = 8;
static constexpr int Tdim = 2048;
static constexpr int Ddim = 2048;
static constexpr int Mdim = Bdim * Tdim;          // 16384
static constexpr int BM = 128, BN = 128, BK = 64;
static constexpr int KTILES = Ddim / BK;          // 32
static constexpr int MTILES = Mdim / BM;          // 128
static constexpr int NTILES = Ddim / BN;          // 16
static constexpr int STAGES = 3;
static constexpr int A_TILE_BYTES = BM * BK * 2;  // 16384
static constexpr int STAGE_BYTES = 2 * A_TILE_BYTES;      // 32768 (A+B)
static constexpr int DYN_BYTES = STAGES * STAGE_BYTES;    // 98304

static constexpr int CCH = 16;                    // scan chunks per channel
static constexpr int LCH = Tdim / CCH;            // 128 steps per chunk
static constexpr int NCH = Bdim * Ddim;           // 16384 channels

// Scratch (device globals: allocation-free rule)
__device__ __half g_ugh[(size_t)Mdim * Ddim];         // 64 MB (u_g fp16)
__device__ __half g_uh[(size_t)Mdim * Ddim];          // 64 MB
__device__ __half g_wh[(size_t)Ddim * Ddim];          // 8 MB
__device__ float  g_partials[(size_t)MTILES * Ddim];
__device__ float  g_rp[64 * 4];                       // rank-4 partials (8 slices x 8 b)
__device__ float  g_carry[MTILES * Ddim];             // carry[(b*16+chunk)*D + dd]
__device__ float  g_state[MTILES * Ddim];

// ---------------- helpers ----------------
__device__ __forceinline__ uint32_t cvta_shared(const void* p) {
    uint32_t a;
    asm("{ .reg .u64 t; cvta.to.shared.u64 t, %1; cvt.u32.u64 %0, t; }"
        : "=r"(a) : "l"(p));
    return a;
}
__device__ __forceinline__ void cp_async16(uint32_t saddr, const void* gaddr) {
    asm volatile("cp.async.cg.shared.global [%0], [%1], 16;"
                 :: "r"(saddr), "l"(gaddr) : "memory");
}
__device__ __forceinline__ void cp_commit() {
    asm volatile("cp.async.commit_group;" ::: "memory");
}
template <int N>
__device__ __forceinline__ void cp_wait() {
    asm volatile("cp.async.wait_group %0;" :: "n"(N) : "memory");
}
__device__ __forceinline__ uint32_t sw128(uint32_t off) {
    return off ^ ((off >> 3) & 0x70);
}
__device__ __forceinline__ void ldsm_x4(uint32_t* r, uint32_t addr) {
    asm volatile("ldmatrix.sync.aligned.m8n8.x4.shared.b16 {%0,%1,%2,%3}, [%4];"
                 : "=r"(r[0]), "=r"(r[1]), "=r"(r[2]), "=r"(r[3]) : "r"(addr));
}
__device__ __forceinline__ void mma_f16(float& d0, float& d1, float& d2, float& d3,
                                        uint32_t a0, uint32_t a1, uint32_t a2,
                                        uint32_t a3, uint32_t b0, uint32_t b1) {
    asm volatile(
        "mma.sync.aligned.m16n8k16.row.col.f32.f16.f16.f32 "
        "{%0,%1,%2,%3}, {%4,%5,%6,%7}, {%8,%9}, {%0,%1,%2,%3};"
        : "+f"(d0), "+f"(d1), "+f"(d2), "+f"(d3)
        : "r"(a0), "r"(a1), "r"(a2), "r"(a3), "r"(b0), "r"(b1));
}

// ============ Kernel 0: fp32 -> fp16 convert (vectorized) ============
__global__ __launch_bounds__(256)
void conv_half(const float* __restrict__ src, __half* __restrict__ dst) {
    const size_t i = (size_t)blockIdx.x * 256 + threadIdx.x;
    float4 v = ((const float4*)src)[i];
    ((__half2*)dst)[2 * i] = __floats2half2_rn(v.x, v.y);
    ((__half2*)dst)[2 * i + 1] = __floats2half2_rn(v.z, v.w);
}

// ======= Kernel 1: fp16 mma.sync GEMM + gate epilogue + scan carries =======
__global__ __launch_bounds__(256, 2)
void gemm_gate_mma(const float* __restrict__ gb,
                   const float* __restrict__ av,
                   const float* __restrict__ bv) {
    extern __shared__ __align__(128) char sm[];
    __shared__ float s_gb[BN];
    __shared__ float s_aa[BN];
    __shared__ float s_bb[BN];
    __shared__ float s_red[2][BN];
    __shared__ float s_car[2][BN];

    const int tid = threadIdx.x;
    const int wid = tid >> 5;
    const int lane = tid & 31;
    const int g = lane >> 2;        // octet row (0..7)
    const int t = lane & 3;         // thread-in-group (0..3)
    const int grp = lane >> 3;      // ldmatrix address group (0..3)
    const int lrow = lane & 7;
    const int warp_m = wid >> 2;    // 0..1  (64-row slabs)
    const int warp_n = wid & 3;     // 0..3  (32-col slabs)
    const int n0 = blockIdx.x * BN;
    const int m0 = blockIdx.y * BM;
    const uint32_t smem_base = cvta_shared(sm);

    const int rowoff_a = ((grp & 1) << 3) + lrow;
    const int koff_a = (grp >> 1) << 4;
    const int rowoff_b = ((grp >> 1) << 3) + lrow;
    const int koff_b = (grp & 1) << 4;

    for (int i = tid; i < BN; i += 256) {
        s_gb[i] = gb[n0 + i];
        s_aa[i] = tanhf(av[n0 + i]);
        s_bb[i] = bv[n0 + i];
    }

    float acc[4][4][4];             // [m16 tile][n8 tile][c0..c3]
#pragma unroll
    for (int i = 0; i < 4; i++)
#pragma unroll
        for (int j = 0; j < 4; j++)
#pragma unroll
            for (int r = 0; r < 4; r++) acc[i][j][r] = 0.f;

    auto load_tile = [&](int kt, int s) {
        const uint32_t ab = smem_base + (uint32_t)s * STAGE_BYTES;
        const uint32_t bb = ab + A_TILE_BYTES;
        const __half* gA = g_uh + (size_t)m0 * Ddim + kt * BK;
        const __half* gB = g_wh + (size_t)n0 * Ddim + kt * BK;
#pragma unroll
        for (int i = 0; i < 4; i++) {
            const int id = tid + i * 256;
            const int row = id >> 3, c = id & 7;
            cp_async16(ab + sw128((uint32_t)(row * 128 + c * 16)),
                       gA + (size_t)row * Ddim + c * 8);
        }
#pragma unroll
        for (int i = 0; i < 4; i++) {
            const int id = tid + i * 256;
            const int row = id >> 3, c = id & 7;
            cp_async16(bb + sw128((uint32_t)(row * 128 + c * 16)),
                       gB + (size_t)row * Ddim + c * 8);
        }
    };

    auto compute_tile = [&](int st) {
        const uint32_t ab = smem_base + (uint32_t)st * STAGE_BYTES;
        const uint32_t bb = ab + A_TILE_BYTES;
#pragma unroll
        for (int s = 0; s < BK / 16; s++) {          // 4 k-steps of 16
            uint32_t a[4][4], b[2][4];
#pragma unroll
            for (int i = 0; i < 4; i++) {
                const int row = warp_m * 64 + i * 16 + rowoff_a;
                ldsm_x4(a[i], ab + sw128((uint32_t)(row * 128 + s * 32 + koff_a)));
            }
#pragma unroll
            for (int jj = 0; jj < 2; jj++) {
                const int row = warp_n * 32 + jj * 16 + rowoff_b;
                ldsm_x4(b[jj], bb + sw128((uint32_t)(row * 128 + s * 32 + koff_b)));
            }
#pragma unroll
            for (int i = 0; i < 4; i++)
#pragma unroll
                for (int j = 0; j < 4; j++)
                    mma_f16(acc[i][j][0], acc[i][j][1], acc[i][j][2], acc[i][j][3],
                            a[i][0], a[i][1], a[i][2], a[i][3],
                            b[j >> 1][(j & 1) * 2 + 0], b[j >> 1][(j & 1) * 2 + 1]);
        }
    };

    // ---- 3-stage pipeline, one syncthreads per iteration ----
    load_tile(0, 0);
    cp_commit();
    load_tile(1, 1);
    cp_commit();
#pragma unroll 1
    for (int kt = 0; kt < KTILES; ++kt) {
        cp_wait<1>();
        __syncthreads();
        if (kt + 2 < KTILES) load_tile(kt + 2, (kt + 2) % STAGES);
        cp_commit();
        compute_tile(kt % STAGES);
    }

    // ---- epilogue: sigmoid gate, u_g (fp16), colsum + carry reductions ----
    // Tile rows m0..m0+127 are exactly chunk (by%16) of batch (by/16):
    // carry[col] = sum_r aa^(127-r)*bb*ug[r].  Per-thread rows have uniform
    // stride 8 -> Horner with ratio aa^8, absolute weight bb*aa^(71-base).
    float csum[4][2];
#pragma unroll
    for (int j = 0; j < 4; j++) { csum[j][0] = 0.f; csum[j][1] = 0.f; }

#pragma unroll
    for (int j = 0; j < 4; j++) {
        const int col = warp_n * 32 + j * 8 + 2 * t;
        const float gb0 = s_gb[col];
        const float gb1 = s_gb[col + 1];
        const float aa0 = s_aa[col], aa1 = s_aa[col + 1];
        float a8_0 = aa0 * aa0; a8_0 *= a8_0; a8_0 *= a8_0;   // aa^8
        float a8_1 = aa1 * aa1; a8_1 *= a8_1; a8_1 *= a8_1;
        float Q0 = 0.f, Q1 = 0.f;
#pragma unroll
        for (int i = 0; i < 4; i++) {
#pragma unroll
            for (int h = 0; h < 2; h++) {
                const int row = warp_m * 64 + i * 16 + h * 8 + g;
                const size_t off = (size_t)(m0 + row) * Ddim + n0 + col;
                const __half2 uu = *(const __half2*)(g_uh + off);
                const float l0 = acc[i][j][h * 2 + 0] + gb0;
                const float l1 = acc[i][j][h * 2 + 1] + gb1;
                const float ug0 = __half2float(uu.x) * (1.f / (1.f + __expf(-l0)));
                const float ug1 = __half2float(uu.y) * (1.f / (1.f + __expf(-l1)));
                const __half2 ugh = __floats2half2_rn(ug0, ug1);
                *(__half2*)(g_ugh + off) = ugh;
                // carry uses the ROUNDED values (matches what p3 replays)
                const float ur0 = __half2float(ugh.x);
                const float ur1 = __half2float(ugh.y);
                Q0 = fmaf(Q0, a8_0, ur0);
                Q1 = fmaf(Q1, a8_1, ur1);
                csum[j][0] += ug0;
                csum[j][1] += ug1;
            }
        }
        // absolute weight: bb * aa^(71 - warp_m*64 - g)
        // exponent e = (warp_m ? 7-g : 71-g); aa^(7-g) by loop, *aa^64 if warp_m==0
        float p0 = 1.f, p1 = 1.f;
        for (int k = 0; k < 7 - g; k++) { p0 *= aa0; p1 *= aa1; }
        if (warp_m == 0) {
            float a64_0 = a8_0 * a8_0; a64_0 *= a64_0; a64_0 *= a64_0;  // aa^64
            float a64_1 = a8_1 * a8_1; a64_1 *= a64_1; a64_1 *= a64_1;
            p0 *= a64_0; p1 *= a64_1;
        }
        float P0 = Q0 * p0 * s_bb[col];
        float P1 = Q1 * p1 * s_bb[col + 1];
#pragma unroll
        for (int mask = 16; mask >= 4; mask >>= 1) {
            P0 += __shfl_xor_sync(0xffffffffu, P0, mask);
            P1 += __shfl_xor_sync(0xffffffffu, P1, mask);
        }
        if (g == 0) {
            s_car[warp_m][col] = P0;
            s_car[warp_m][col + 1] = P1;
        }
    }
#pragma unroll
    for (int j = 0; j < 4; j++) {
#pragma unroll
        for (int mask = 16; mask >= 4; mask >>= 1) {
            csum[j][0] += __shfl_xor_sync(0xffffffffu, csum[j][0], mask);
            csum[j][1] += __shfl_xor_sync(0xffffffffu, csum[j][1], mask);
        }
    }
    if (g == 0) {
#pragma unroll
        for (int j = 0; j < 4; j++) {
            s_red[warp_m][warp_n * 32 + j * 8 + 2 * t] = csum[j][0];
            s_red[warp_m][warp_n * 32 + j * 8 + 2 * t + 1] = csum[j][1];
        }
    }
    __syncthreads();
    if (tid < BN) {
        g_partials[(size_t)blockIdx.y * Ddim + n0 + tid] =
            s_red[0][tid] + s_red[1][tid];
        g_carry[(size_t)blockIdx.y * Ddim + n0 + tid] =
            s_car[0][tid] + s_car[1][tid];
    }
}

// ==== Kernel 2: g_rp[(b*8+slice)][r] partial rank-4 sums (64 blocks) =======
__global__ __launch_bounds__(256)
void rvec_part(const float* __restrict__ dlru) {   // [D, 4]
    const int blk = blockIdx.x;      // 0..63
    const int b = blk >> 3;
    const int slice = blk & 7;
    const int tid = threadIdx.x;     // 256
    __shared__ float s_m[8][4];
    const int e = slice * 256 + tid;
    float s = 0.f;
#pragma unroll
    for (int i = 0; i < 16; i++)
        s += g_partials[(size_t)(b * 16 + i) * Ddim + e];
    const float mean = s * (1.0f / Tdim);
    const float4 w = ((const float4*)dlru)[e];
    float a0 = mean * w.x, a1 = mean * w.y, a2 = mean * w.z, a3 = mean * w.w;
#pragma unroll
    for (int mask = 16; mask >= 1; mask >>= 1) {
        a0 += __shfl_xor_sync(0xffffffffu, a0, mask);
        a1 += __shfl_xor_sync(0xffffffffu, a1, mask);
        a2 += __shfl_xor_sync(0xffffffffu, a2, mask);
        a3 += __shfl_xor_sync(0xffffffffu, a3, mask);
    }
    const int wid = tid >> 5;
    if ((tid & 31) == 0) {
        s_m[wid][0] = a0; s_m[wid][1] = a1; s_m[wid][2] = a2; s_m[wid][3] = a3;
    }
    __syncthreads();
    if (tid < 4) {
        float r = 0.f;
#pragma unroll
        for (int i = 0; i < 8; i++) r += s_m[i][tid];
        g_rp[blk * 4 + tid] = r;
    }
}

// ==== Kernel 3b: per-channel carry combine (aa^L exact squarings) =========
__global__ __launch_bounds__(256)
void scan_p2(const float* __restrict__ av) {
    const int q = blockIdx.x * 256 + threadIdx.x;       // 0 .. NCH-1
    const int dd = q & (Ddim - 1);
    const int b = q >> 11;
    const float aa = tanhf(av[dd]);
    float aL = aa;                                      // aa^128 = 7 squarings
#pragma unroll
    for (int i = 0; i < 7; i++) aL *= aL;
    float s = 0.f;
#pragma unroll
    for (int j = 0; j < CCH; j++) {
        const int idx = (b * CCH + j) * Ddim + dd;
        g_state[idx] = s;                               // state entering chunk j
        s = fmaf(aL, s, g_carry[idx]);
    }
}

// ==== Kernel 3c: replay chunks with true init state, write y ==============
__global__ __launch_bounds__(256)
void scan_p3(const float* __restrict__ av,
             const float* __restrict__ bv,
             const float* __restrict__ cv,
             const float* __restrict__ dvec,
             const float* __restrict__ dlrv,   // [4, D]
             float* __restrict__ Y) {
    const int gidx = blockIdx.x * 256 + threadIdx.x;   // 0 .. NCH*CCH-1
    const int dd = gidx & (Ddim - 1);
    const int rest = gidx >> 11;                        // b*CCH + chunk
    const int b = rest >> 4;
    const float aa = tanhf(av[dd]);
    const float bb = bv[dd];
    const float cc = cv[dd];
    float r0 = 0.f, r1 = 0.f, r2 = 0.f, r3 = 0.f;
#pragma unroll
    for (int sl = 0; sl < 8; sl++) {
        const float4 rp = ((const float4*)g_rp)[b * 8 + sl];
        r0 += rp.x; r1 += rp.y; r2 += rp.z; r3 += rp.w;
    }
    const float de = dvec[dd] +
        0.25f * (r0 * dlrv[dd] + r1 * dlrv[Ddim + dd] +
                 r2 * dlrv[2 * Ddim + dd] + r3 * dlrv[3 * Ddim + dd]);
    const __half* p = g_ugh + (size_t)rest * LCH * Ddim + dd;
    float* q = Y + (size_t)rest * LCH * Ddim + dd;
    float s = g_state[gidx];
#pragma unroll 1
    for (int t0 = 0; t0 < LCH; t0 += 8) {
        __half x[8];
#pragma unroll
        for (int j = 0; j < 8; j++) x[j] = p[(size_t)(t0 + j) * Ddim];
#pragma unroll
        for (int j = 0; j < 8; j++) {
            const float xf = __half2float(x[j]);
            s = fmaf(aa, s, bb * xf);
            q[(size_t)(t0 + j) * Ddim] = fmaf(cc, s, de * xf);
        }
    }
}

extern "C" void kernel_launch(void* const* d_in, const int* in_sizes, int n_in,
                              void* d_out, int out_size) {
    const float* U    = (const float*)d_in[0];  // [B,T,D]
    const float* av   = (const float*)d_in[1];  // [D]
    const float* bv   = (const float*)d_in[2];  // [D]
    const float* cv   = (const float*)d_in[3];  // [D]
    const float* dv   = (const float*)d_in[4];  // [D]
    const float* gw   = (const float*)d_in[5];  // [D,D]
    const float* gbp  = (const float*)d_in[6];  // [D]
    const float* dlru = (const float*)d_in[7];  // [D,4]
    const float* dlrv = (const float*)d_in[8];  // [4,D]
    float* Y = (float*)d_out;

    __half* uh_p; cudaGetSymbolAddress((void**)&uh_p, g_uh);
    __half* wh_p; cudaGetSymbolAddress((void**)&wh_p, g_wh);

    conv_half<<<(Mdim * (size_t)Ddim / 4) / 256, 256>>>(U, uh_p);
    conv_half<<<((size_t)Ddim * Ddim / 4) / 256, 256>>>(gw, wh_p);

    cudaFuncSetAttribute(gemm_gate_mma,
                         cudaFuncAttributeMaxDynamicSharedMemorySize, DYN_BYTES);
    gemm_gate_mma<<<dim3(NTILES, MTILES), 256, DYN_BYTES>>>(gbp, av, bv);
    rvec_part<<<64, 256>>>(dlru);
    scan_p2<<<NCH / 256, 256>>>(av);
    scan_p3<<<(NCH * CCH) / 256, 256>>>(av, bv, cv, dv, dlrv, Y);
}

// round 12
// speedup vs baseline: 1.3941x; 1.0182x over previous
// SSMDiagScan_84731114816205 — gated diagonal SSM
//   y = c * scan(aa, b*u_g) + d_eff * u_g,  u_g = u * sigmoid(u @ W^T + gb)
// K0: single fused fp32->fp16 convert of U and W
// K1: fp16 mma.sync m16n8k16 GEMM (legacy-tensor floor ~390us), fused epilogue:
//     sigmoid gate, fp16 u_g, colsum partials, AND per-(chunk,channel) scan
//     carries (Horner, ratio aa^8) — scan phase 1 on K1's idle pipes.
// K2: rank-4 partial reduction (64 blocks)
// K3: chunk replay + output; entry state recombined from carries inline
//     (p2 merged into p3; bitwise-identical order), d_eff inline.

#include <cuda_runtime.h>
#include <cuda_fp16.h>
#include <cstdint>

static constexpr int Bdim = 8;
static constexpr int Tdim = 2048;
static constexpr int Ddim = 2048;
static constexpr int Mdim = Bdim * Tdim;          // 16384
static constexpr int BM = 128, BN = 128, BK = 64;
static constexpr int KTILES = Ddim / BK;          // 32
static constexpr int MTILES = Mdim / BM;          // 128
static constexpr int NTILES = Ddim / BN;          // 16
static constexpr int STAGES = 3;
static constexpr int A_TILE_BYTES = BM * BK * 2;  // 16384
static constexpr int STAGE_BYTES = 2 * A_TILE_BYTES;      // 32768 (A+B)
static constexpr int DYN_BYTES = STAGES * STAGE_BYTES;    // 98304

static constexpr int CCH = 16;                    // scan chunks per channel
static constexpr int LCH = Tdim / CCH;            // 128 steps per chunk
static constexpr int NCH = Bdim * Ddim;           // 16384 channels
static constexpr size_t NU4 = (size_t)Mdim * Ddim / 4;    // U float4 count
static constexpr size_t NW4 = (size_t)Ddim * Ddim / 4;    // W float4 count

// Scratch (device globals: allocation-free rule)
__device__ __half g_ugh[(size_t)Mdim * Ddim];         // 64 MB (u_g fp16)
__device__ __half g_uh[(size_t)Mdim * Ddim];          // 64 MB
__device__ __half g_wh[(size_t)Ddim * Ddim];          // 8 MB
__device__ float  g_partials[(size_t)MTILES * Ddim];
__device__ float  g_rp[64 * 4];                       // rank-4 partials
__device__ float  g_carry[MTILES * Ddim];             // carry[(b*16+chunk)*D + dd]

// ---------------- helpers ----------------
__device__ __forceinline__ uint32_t cvta_shared(const void* p) {
    uint32_t a;
    asm("{ .reg .u64 t; cvta.to.shared.u64 t, %1; cvt.u32.u64 %0, t; }"
        : "=r"(a) : "l"(p));
    return a;
}
__device__ __forceinline__ void cp_async16(uint32_t saddr, const void* gaddr) {
    asm volatile("cp.async.cg.shared.global [%0], [%1], 16;"
                 :: "r"(saddr), "l"(gaddr) : "memory");
}
__device__ __forceinline__ void cp_commit() {
    asm volatile("cp.async.commit_group;" ::: "memory");
}
template <int N>
__device__ __forceinline__ void cp_wait() {
    asm volatile("cp.async.wait_group %0;" :: "n"(N) : "memory");
}
__device__ __forceinline__ uint32_t sw128(uint32_t off) {
    return off ^ ((off >> 3) & 0x70);
}
__device__ __forceinline__ void ldsm_x4(uint32_t* r, uint32_t addr) {
    asm volatile("ldmatrix.sync.aligned.m8n8.x4.shared.b16 {%0,%1,%2,%3}, [%4];"
                 : "=r"(r[0]), "=r"(r[1]), "=r"(r[2]), "=r"(r[3]) : "r"(addr));
}
__device__ __forceinline__ void mma_f16(float& d0, float& d1, float& d2, float& d3,
                                        uint32_t a0, uint32_t a1, uint32_t a2,
                                        uint32_t a3, uint32_t b0, uint32_t b1) {
    asm volatile(
        "mma.sync.aligned.m16n8k16.row.col.f32.f16.f16.f32 "
        "{%0,%1,%2,%3}, {%4,%5,%6,%7}, {%8,%9}, {%0,%1,%2,%3};"
        : "+f"(d0), "+f"(d1), "+f"(d2), "+f"(d3)
        : "r"(a0), "r"(a1), "r"(a2), "r"(a3), "r"(b0), "r"(b1));
}

// ===== Kernel 0: fused fp32 -> fp16 convert of U then W (one launch) =====
__global__ __launch_bounds__(256)
void conv_both(const float* __restrict__ u_src, const float* __restrict__ w_src,
               __half* __restrict__ u_dst, __half* __restrict__ w_dst) {
    const size_t i = (size_t)blockIdx.x * 256 + threadIdx.x;
    const float* src;
    __half* dst;
    size_t idx;
    if (i < NU4) { src = u_src; dst = u_dst; idx = i; }
    else         { src = w_src; dst = w_dst; idx = i - NU4; }
    float4 v = ((const float4*)src)[idx];
    ((__half2*)dst)[2 * idx] = __floats2half2_rn(v.x, v.y);
    ((__half2*)dst)[2 * idx + 1] = __floats2half2_rn(v.z, v.w);
}

// ======= Kernel 1: fp16 mma.sync GEMM + gate epilogue + scan carries =======
__global__ __launch_bounds__(256, 2)
void gemm_gate_mma(const float* __restrict__ gb,
                   const float* __restrict__ av,
                   const float* __restrict__ bv) {
    extern __shared__ __align__(128) char sm[];
    __shared__ float s_gb[BN];
    __shared__ float s_aa[BN];
    __shared__ float s_bb[BN];
    __shared__ float s_red[2][BN];
    __shared__ float s_car[2][BN];

    const int tid = threadIdx.x;
    const int wid = tid >> 5;
    const int lane = tid & 31;
    const int g = lane >> 2;        // octet row (0..7)
    const int t = lane & 3;         // thread-in-group (0..3)
    const int grp = lane >> 3;      // ldmatrix address group (0..3)
    const int lrow = lane & 7;
    const int warp_m = wid >> 2;    // 0..1  (64-row slabs)
    const int warp_n = wid & 3;     // 0..3  (32-col slabs)
    const int n0 = blockIdx.x * BN;
    const int m0 = blockIdx.y * BM;
    const uint32_t smem_base = cvta_shared(sm);

    const int rowoff_a = ((grp & 1) << 3) + lrow;
    const int koff_a = (grp >> 1) << 4;
    const int rowoff_b = ((grp >> 1) << 3) + lrow;
    const int koff_b = (grp & 1) << 4;

    for (int i = tid; i < BN; i += 256) {
        s_gb[i] = gb[n0 + i];
        s_aa[i] = tanhf(av[n0 + i]);
        s_bb[i] = bv[n0 + i];
    }

    float acc[4][4][4];             // [m16 tile][n8 tile][c0..c3]
#pragma unroll
    for (int i = 0; i < 4; i++)
#pragma unroll
        for (int j = 0; j < 4; j++)
#pragma unroll
            for (int r = 0; r < 4; r++) acc[i][j][r] = 0.f;

    auto load_tile = [&](int kt, int s) {
        const uint32_t ab = smem_base + (uint32_t)s * STAGE_BYTES;
        const uint32_t bb = ab + A_TILE_BYTES;
        const __half* gA = g_uh + (size_t)m0 * Ddim + kt * BK;
        const __half* gB = g_wh + (size_t)n0 * Ddim + kt * BK;
#pragma unroll
        for (int i = 0; i < 4; i++) {
            const int id = tid + i * 256;
            const int row = id >> 3, c = id & 7;
            cp_async16(ab + sw128((uint32_t)(row * 128 + c * 16)),
                       gA + (size_t)row * Ddim + c * 8);
        }
#pragma unroll
        for (int i = 0; i < 4; i++) {
            const int id = tid + i * 256;
            const int row = id >> 3, c = id & 7;
            cp_async16(bb + sw128((uint32_t)(row * 128 + c * 16)),
                       gB + (size_t)row * Ddim + c * 8);
        }
    };

    auto compute_tile = [&](int st) {
        const uint32_t ab = smem_base + (uint32_t)st * STAGE_BYTES;
        const uint32_t bb = ab + A_TILE_BYTES;
#pragma unroll
        for (int s = 0; s < BK / 16; s++) {          // 4 k-steps of 16
            uint32_t a[4][4], b[2][4];
#pragma unroll
            for (int i = 0; i < 4; i++) {
                const int row = warp_m * 64 + i * 16 + rowoff_a;
                ldsm_x4(a[i], ab + sw128((uint32_t)(row * 128 + s * 32 + koff_a)));
            }
#pragma unroll
            for (int jj = 0; jj < 2; jj++) {
                const int row = warp_n * 32 + jj * 16 + rowoff_b;
                ldsm_x4(b[jj], bb + sw128((uint32_t)(row * 128 + s * 32 + koff_b)));
            }
#pragma unroll
            for (int i = 0; i < 4; i++)
#pragma unroll
                for (int j = 0; j < 4; j++)
                    mma_f16(acc[i][j][0], acc[i][j][1], acc[i][j][2], acc[i][j][3],
                            a[i][0], a[i][1], a[i][2], a[i][3],
                            b[j >> 1][(j & 1) * 2 + 0], b[j >> 1][(j & 1) * 2 + 1]);
        }
    };

    // ---- 3-stage pipeline, one syncthreads per iteration ----
    load_tile(0, 0);
    cp_commit();
    load_tile(1, 1);
    cp_commit();
#pragma unroll 1
    for (int kt = 0; kt < KTILES; ++kt) {
        cp_wait<1>();
        __syncthreads();
        if (kt + 2 < KTILES) load_tile(kt + 2, (kt + 2) % STAGES);
        cp_commit();
        compute_tile(kt % STAGES);
    }

    // ---- epilogue: sigmoid gate, u_g (fp16), colsum + carry reductions ----
    float csum[4][2];
#pragma unroll
    for (int j = 0; j < 4; j++) { csum[j][0] = 0.f; csum[j][1] = 0.f; }

#pragma unroll
    for (int j = 0; j < 4; j++) {
        const int col = warp_n * 32 + j * 8 + 2 * t;
        const float gb0 = s_gb[col];
        const float gb1 = s_gb[col + 1];
        const float aa0 = s_aa[col], aa1 = s_aa[col + 1];
        float a8_0 = aa0 * aa0; a8_0 *= a8_0; a8_0 *= a8_0;   // aa^8
        float a8_1 = aa1 * aa1; a8_1 *= a8_1; a8_1 *= a8_1;
        float Q0 = 0.f, Q1 = 0.f;
#pragma unroll
        for (int i = 0; i < 4; i++) {
#pragma unroll
            for (int h = 0; h < 2; h++) {
                const int row = warp_m * 64 + i * 16 + h * 8 + g;
                const size_t off = (size_t)(m0 + row) * Ddim + n0 + col;
                const __half2 uu = *(const __half2*)(g_uh + off);
                const float l0 = acc[i][j][h * 2 + 0] + gb0;
                const float l1 = acc[i][j][h * 2 + 1] + gb1;
                const float ug0 = __half2float(uu.x) * (1.f / (1.f + __expf(-l0)));
                const float ug1 = __half2float(uu.y) * (1.f / (1.f + __expf(-l1)));
                const __half2 ugh = __floats2half2_rn(ug0, ug1);
                *(__half2*)(g_ugh + off) = ugh;
                const float ur0 = __half2float(ugh.x);
                const float ur1 = __half2float(ugh.y);
                Q0 = fmaf(Q0, a8_0, ur0);
                Q1 = fmaf(Q1, a8_1, ur1);
                csum[j][0] += ug0;
                csum[j][1] += ug1;
            }
        }
        float p0 = 1.f, p1 = 1.f;
        for (int k = 0; k < 7 - g; k++) { p0 *= aa0; p1 *= aa1; }
        if (warp_m == 0) {
            float a64_0 = a8_0 * a8_0; a64_0 *= a64_0; a64_0 *= a64_0;  // aa^64
            float a64_1 = a8_1 * a8_1; a64_1 *= a64_1; a64_1 *= a64_1;
            p0 *= a64_0; p1 *= a64_1;
        }
        float P0 = Q0 * p0 * s_bb[col];
        float P1 = Q1 * p1 * s_bb[col + 1];
#pragma unroll
        for (int mask = 16; mask >= 4; mask >>= 1) {
            P0 += __shfl_xor_sync(0xffffffffu, P0, mask);
            P1 += __shfl_xor_sync(0xffffffffu, P1, mask);
        }
        if (g == 0) {
            s_car[warp_m][col] = P0;
            s_car[warp_m][col + 1] = P1;
        }
    }
#pragma unroll
    for (int j = 0; j < 4; j++) {
#pragma unroll
        for (int mask = 16; mask >= 4; mask >>= 1) {
            csum[j][0] += __shfl_xor_sync(0xffffffffu, csum[j][0], mask);
            csum[j][1] += __shfl_xor_sync(0xffffffffu, csum[j][1], mask);
        }
    }
    if (g == 0) {
#pragma unroll
        for (int j = 0; j < 4; j++) {
            s_red[warp_m][warp_n * 32 + j * 8 + 2 * t] = csum[j][0];
            s_red[warp_m][warp_n * 32 + j * 8 + 2 * t + 1] = csum[j][1];
        }
    }
    __syncthreads();
    if (tid < BN) {
        g_partials[(size_t)blockIdx.y * Ddim + n0 + tid] =
            s_red[0][tid] + s_red[1][tid];
        g_carry[(size_t)blockIdx.y * Ddim + n0 + tid] =
            s_car[0][tid] + s_car[1][tid];
    }
}

// ==== Kernel 2: g_rp[(b*8+slice)][r] partial rank-4 sums (64 blocks) =======
__global__ __launch_bounds__(256)
void rvec_part(const float* __restrict__ dlru) {   // [D, 4]
    const int blk = blockIdx.x;      // 0..63
    const int b = blk >> 3;
    const int slice = blk & 7;
    const int tid = threadIdx.x;     // 256
    __shared__ float s_m[8][4];
    const int e = slice * 256 + tid;
    float s = 0.f;
#pragma unroll
    for (int i = 0; i < 16; i++)
        s += g_partials[(size_t)(b * 16 + i) * Ddim + e];
    const float mean = s * (1.0f / Tdim);
    const float4 w = ((const float4*)dlru)[e];
    float a0 = mean * w.x, a1 = mean * w.y, a2 = mean * w.z, a3 = mean * w.w;
#pragma unroll
    for (int mask = 16; mask >= 1; mask >>= 1) {
        a0 += __shfl_xor_sync(0xffffffffu, a0, mask);
        a1 += __shfl_xor_sync(0xffffffffu, a1, mask);
        a2 += __shfl_xor_sync(0xffffffffu, a2, mask);
        a3 += __shfl_xor_sync(0xffffffffu, a3, mask);
    }
    const int wid = tid >> 5;
    if ((tid & 31) == 0) {
        s_m[wid][0] = a0; s_m[wid][1] = a1; s_m[wid][2] = a2; s_m[wid][3] = a3;
    }
    __syncthreads();
    if (tid < 4) {
        float r = 0.f;
#pragma unroll
        for (int i = 0; i < 8; i++) r += s_m[i][tid];
        g_rp[blk * 4 + tid] = r;
    }
}

// ==== Kernel 3: chunk replay + output; entry state recombined inline ======
__global__ __launch_bounds__(256)
void scan_p3(const float* __restrict__ av,
             const float* __restrict__ bv,
             const float* __restrict__ cv,
             const float* __restrict__ dvec,
             const float* __restrict__ dlrv,   // [4, D]
             float* __restrict__ Y) {
    const int gidx = blockIdx.x * 256 + threadIdx.x;   // 0 .. NCH*CCH-1
    const int dd = gidx & (Ddim - 1);
    const int rest = gidx >> 11;                        // b*CCH + chunk
    const int b = rest >> 4;
    const int chunk = rest & (CCH - 1);
    const float aa = tanhf(av[dd]);
    const float bb = bv[dd];
    const float cc = cv[dd];
    float r0 = 0.f, r1 = 0.f, r2 = 0.f, r3 = 0.f;
#pragma unroll
    for (int sl = 0; sl < 8; sl++) {
        const float4 rp = ((const float4*)g_rp)[b * 8 + sl];
        r0 += rp.x; r1 += rp.y; r2 += rp.z; r3 += rp.w;
    }
    const float de = dvec[dd] +
        0.25f * (r0 * dlrv[dd] + r1 * dlrv[Ddim + dd] +
                 r2 * dlrv[2 * Ddim + dd] + r3 * dlrv[3 * Ddim + dd]);
    // entry state: replicate p2's exact iteration order for chunks < chunk
    float aL = aa;                                      // aa^128 = 7 squarings
#pragma unroll
    for (int i = 0; i < 7; i++) aL *= aL;
    float s = 0.f;
#pragma unroll 1
    for (int j = 0; j < chunk; j++)
        s = fmaf(aL, s, g_carry[(b * CCH + j) * Ddim + dd]);
    const __half* p = g_ugh + (size_t)rest * LCH * Ddim + dd;
    float* q = Y + (size_t)rest * LCH * Ddim + dd;
#pragma unroll 1
    for (int t0 = 0; t0 < LCH; t0 += 8) {
        __half x[8];
#pragma unroll
        for (int j = 0; j < 8; j++) x[j] = p[(size_t)(t0 + j) * Ddim];
#pragma unroll
        for (int j = 0; j < 8; j++) {
            const float xf = __half2float(x[j]);
            s = fmaf(aa, s, bb * xf);
            q[(size_t)(t0 + j) * Ddim] = fmaf(cc, s, de * xf);
        }
    }
}

extern "C" void kernel_launch(void* const* d_in, const int* in_sizes, int n_in,
                              void* d_out, int out_size) {
    const float* U    = (const float*)d_in[0];  // [B,T,D]
    const float* av   = (const float*)d_in[1];  // [D]
    const float* bv   = (const float*)d_in[2];  // [D]
    const float* cv   = (const float*)d_in[3];  // [D]
    const float* dv   = (const float*)d_in[4];  // [D]
    const float* gw   = (const float*)d_in[5];  // [D,D]
    const float* gbp  = (const float*)d_in[6];  // [D]
    const float* dlru = (const float*)d_in[7];  // [D,4]
    const float* dlrv = (const float*)d_in[8];  // [4,D]
    float* Y = (float*)d_out;

    __half* uh_p; cudaGetSymbolAddress((void**)&uh_p, g_uh);
    __half* wh_p; cudaGetSymbolAddress((void**)&wh_p, g_wh);

    conv_both<<<(unsigned)((NU4 + NW4) / 256), 256>>>(U, gw, uh_p, wh_p);

    cudaFuncSetAttribute(gemm_gate_mma,
                         cudaFuncAttributeMaxDynamicSharedMemorySize, DYN_BYTES);
    gemm_gate_mma<<<dim3(NTILES, MTILES), 256, DYN_BYTES>>>(gbp, av, bv);
    rvec_part<<<64, 256>>>(dlru);
    scan_p3<<<(NCH * CCH) / 256, 256>>>(av, bv, cv, dv, dlrv, Y);
}

// round 13
// speedup vs baseline: 1.4067x; 1.0091x over previous
// SSMDiagScan_84731114816205 — gated diagonal SSM
//   y = c * scan(aa, b*u_g) + d_eff * u_g,  u_g = u * sigmoid(u @ W^T + gb)
// K0: single fused fp32->fp16 convert of U and W
// K1: fp16 mma.sync m16n8k16 GEMM (legacy-tensor floor ~382us), fused epilogue:
//     sigmoid gate, fp16 u_g, colsum partials, AND per-(chunk,channel) scan
//     carries (Horner, ratio aa^8) — scan phase 1 on K1's idle pipes.
// K2: rank-4 partial reduction (64 blocks)
// K3: chunk replay + output, 4 channels/thread (uint2 loads, float4 stores,
//     streaming cache hints); entry state recombined from carries inline.

#include <cuda_runtime.h>
#include <cuda_fp16.h>
#include <cstdint>

static constexpr int Bdim = 8;
static constexpr int Tdim = 2048;
static constexpr int Ddim = 2048;
static constexpr int Mdim = Bdim * Tdim;          // 16384
static constexpr int BM = 128, BN = 128, BK = 64;
static constexpr int KTILES = Ddim / BK;          // 32
static constexpr int MTILES = Mdim / BM;          // 128
static constexpr int NTILES = Ddim / BN;          // 16
static constexpr int STAGES = 3;
static constexpr int A_TILE_BYTES = BM * BK * 2;  // 16384
static constexpr int STAGE_BYTES = 2 * A_TILE_BYTES;      // 32768 (A+B)
static constexpr int DYN_BYTES = STAGES * STAGE_BYTES;    // 98304

static constexpr int CCH = 16;                    // scan chunks per channel
static constexpr int LCH = Tdim / CCH;            // 128 steps per chunk
static constexpr int NCH = Bdim * Ddim;           // 16384 channels
static constexpr size_t NU4 = (size_t)Mdim * Ddim / 4;    // U float4 count
static constexpr size_t NW4 = (size_t)Ddim * Ddim / 4;    // W float4 count

// Scratch (device globals: allocation-free rule)
__device__ __half g_ugh[(size_t)Mdim * Ddim];         // 64 MB (u_g fp16)
__device__ __half g_uh[(size_t)Mdim * Ddim];          // 64 MB
__device__ __half g_wh[(size_t)Ddim * Ddim];          // 8 MB
__device__ float  g_partials[(size_t)MTILES * Ddim];
__device__ float  g_rp[64 * 4];                       // rank-4 partials
__device__ float  g_carry[MTILES * Ddim];             // carry[(b*16+chunk)*D + dd]

// ---------------- helpers ----------------
__device__ __forceinline__ uint32_t cvta_shared(const void* p) {
    uint32_t a;
    asm("{ .reg .u64 t; cvta.to.shared.u64 t, %1; cvt.u32.u64 %0, t; }"
        : "=r"(a) : "l"(p));
    return a;
}
__device__ __forceinline__ void cp_async16(uint32_t saddr, const void* gaddr) {
    asm volatile("cp.async.cg.shared.global [%0], [%1], 16;"
                 :: "r"(saddr), "l"(gaddr) : "memory");
}
__device__ __forceinline__ void cp_commit() {
    asm volatile("cp.async.commit_group;" ::: "memory");
}
template <int N>
__device__ __forceinline__ void cp_wait() {
    asm volatile("cp.async.wait_group %0;" :: "n"(N) : "memory");
}
__device__ __forceinline__ uint32_t sw128(uint32_t off) {
    return off ^ ((off >> 3) & 0x70);
}
__device__ __forceinline__ void ldsm_x4(uint32_t* r, uint32_t addr) {
    asm volatile("ldmatrix.sync.aligned.m8n8.x4.shared.b16 {%0,%1,%2,%3}, [%4];"
                 : "=r"(r[0]), "=r"(r[1]), "=r"(r[2]), "=r"(r[3]) : "r"(addr));
}
__device__ __forceinline__ void mma_f16(float& d0, float& d1, float& d2, float& d3,
                                        uint32_t a0, uint32_t a1, uint32_t a2,
                                        uint32_t a3, uint32_t b0, uint32_t b1) {
    asm volatile(
        "mma.sync.aligned.m16n8k16.row.col.f32.f16.f16.f32 "
        "{%0,%1,%2,%3}, {%4,%5,%6,%7}, {%8,%9}, {%0,%1,%2,%3};"
        : "+f"(d0), "+f"(d1), "+f"(d2), "+f"(d3)
        : "r"(a0), "r"(a1), "r"(a2), "r"(a3), "r"(b0), "r"(b1));
}

// ===== Kernel 0: fused fp32 -> fp16 convert of U then W (one launch) =====
__global__ __launch_bounds__(256)
void conv_both(const float* __restrict__ u_src, const float* __restrict__ w_src,
               __half* __restrict__ u_dst, __half* __restrict__ w_dst) {
    const size_t i = (size_t)blockIdx.x * 256 + threadIdx.x;
    const float* src;
    __half* dst;
    size_t idx;
    if (i < NU4) { src = u_src; dst = u_dst; idx = i; }
    else         { src = w_src; dst = w_dst; idx = i - NU4; }
    float4 v = ((const float4*)src)[idx];
    ((__half2*)dst)[2 * idx] = __floats2half2_rn(v.x, v.y);
    ((__half2*)dst)[2 * idx + 1] = __floats2half2_rn(v.z, v.w);
}

// ======= Kernel 1: fp16 mma.sync GEMM + gate epilogue + scan carries =======
__global__ __launch_bounds__(256, 2)
void gemm_gate_mma(const float* __restrict__ gb,
                   const float* __restrict__ av,
                   const float* __restrict__ bv) {
    extern __shared__ __align__(128) char sm[];
    __shared__ float s_gb[BN];
    __shared__ float s_aa[BN];
    __shared__ float s_bb[BN];
    __shared__ float s_red[2][BN];
    __shared__ float s_car[2][BN];

    const int tid = threadIdx.x;
    const int wid = tid >> 5;
    const int lane = tid & 31;
    const int g = lane >> 2;        // octet row (0..7)
    const int t = lane & 3;         // thread-in-group (0..3)
    const int grp = lane >> 3;      // ldmatrix address group (0..3)
    const int lrow = lane & 7;
    const int warp_m = wid >> 2;    // 0..1  (64-row slabs)
    const int warp_n = wid & 3;     // 0..3  (32-col slabs)
    const int n0 = blockIdx.x * BN;
    const int m0 = blockIdx.y * BM;
    const uint32_t smem_base = cvta_shared(sm);

    const int rowoff_a = ((grp & 1) << 3) + lrow;
    const int koff_a = (grp >> 1) << 4;
    const int rowoff_b = ((grp >> 1) << 3) + lrow;
    const int koff_b = (grp & 1) << 4;

    for (int i = tid; i < BN; i += 256) {
        s_gb[i] = gb[n0 + i];
        s_aa[i] = tanhf(av[n0 + i]);
        s_bb[i] = bv[n0 + i];
    }

    float acc[4][4][4];             // [m16 tile][n8 tile][c0..c3]
#pragma unroll
    for (int i = 0; i < 4; i++)
#pragma unroll
        for (int j = 0; j < 4; j++)
#pragma unroll
            for (int r = 0; r < 4; r++) acc[i][j][r] = 0.f;

    auto load_tile = [&](int kt, int s) {
        const uint32_t ab = smem_base + (uint32_t)s * STAGE_BYTES;
        const uint32_t bb = ab + A_TILE_BYTES;
        const __half* gA = g_uh + (size_t)m0 * Ddim + kt * BK;
        const __half* gB = g_wh + (size_t)n0 * Ddim + kt * BK;
#pragma unroll
        for (int i = 0; i < 4; i++) {
            const int id = tid + i * 256;
            const int row = id >> 3, c = id & 7;
            cp_async16(ab + sw128((uint32_t)(row * 128 + c * 16)),
                       gA + (size_t)row * Ddim + c * 8);
        }
#pragma unroll
        for (int i = 0; i < 4; i++) {
            const int id = tid + i * 256;
            const int row = id >> 3, c = id & 7;
            cp_async16(bb + sw128((uint32_t)(row * 128 + c * 16)),
                       gB + (size_t)row * Ddim + c * 8);
        }
    };

    auto compute_tile = [&](int st) {
        const uint32_t ab = smem_base + (uint32_t)st * STAGE_BYTES;
        const uint32_t bb = ab + A_TILE_BYTES;
#pragma unroll
        for (int s = 0; s < BK / 16; s++) {          // 4 k-steps of 16
            uint32_t a[4][4], b[2][4];
#pragma unroll
            for (int i = 0; i < 4; i++) {
                const int row = warp_m * 64 + i * 16 + rowoff_a;
                ldsm_x4(a[i], ab + sw128((uint32_t)(row * 128 + s * 32 + koff_a)));
            }
#pragma unroll
            for (int jj = 0; jj < 2; jj++) {
                const int row = warp_n * 32 + jj * 16 + rowoff_b;
                ldsm_x4(b[jj], bb + sw128((uint32_t)(row * 128 + s * 32 + koff_b)));
            }
#pragma unroll
            for (int i = 0; i < 4; i++)
#pragma unroll
                for (int j = 0; j < 4; j++)
                    mma_f16(acc[i][j][0], acc[i][j][1], acc[i][j][2], acc[i][j][3],
                            a[i][0], a[i][1], a[i][2], a[i][3],
                            b[j >> 1][(j & 1) * 2 + 0], b[j >> 1][(j & 1) * 2 + 1]);
        }
    };

    // ---- 3-stage pipeline, one syncthreads per iteration ----
    load_tile(0, 0);
    cp_commit();
    load_tile(1, 1);
    cp_commit();
#pragma unroll 1
    for (int kt = 0; kt < KTILES; ++kt) {
        cp_wait<1>();
        __syncthreads();
        if (kt + 2 < KTILES) load_tile(kt + 2, (kt + 2) % STAGES);
        cp_commit();
        compute_tile(kt % STAGES);
    }

    // ---- epilogue: sigmoid gate, u_g (fp16), colsum + carry reductions ----
    float csum[4][2];
#pragma unroll
    for (int j = 0; j < 4; j++) { csum[j][0] = 0.f; csum[j][1] = 0.f; }

#pragma unroll
    for (int j = 0; j < 4; j++) {
        const int col = warp_n * 32 + j * 8 + 2 * t;
        const float gb0 = s_gb[col];
        const float gb1 = s_gb[col + 1];
        const float aa0 = s_aa[col], aa1 = s_aa[col + 1];
        float a8_0 = aa0 * aa0; a8_0 *= a8_0; a8_0 *= a8_0;   // aa^8
        float a8_1 = aa1 * aa1; a8_1 *= a8_1; a8_1 *= a8_1;
        float Q0 = 0.f, Q1 = 0.f;
#pragma unroll
        for (int i = 0; i < 4; i++) {
#pragma unroll
            for (int h = 0; h < 2; h++) {
                const int row = warp_m * 64 + i * 16 + h * 8 + g;
                const size_t off = (size_t)(m0 + row) * Ddim + n0 + col;
                const __half2 uu = *(const __half2*)(g_uh + off);
                const float l0 = acc[i][j][h * 2 + 0] + gb0;
                const float l1 = acc[i][j][h * 2 + 1] + gb1;
                const float ug0 = __half2float(uu.x) * (1.f / (1.f + __expf(-l0)));
                const float ug1 = __half2float(uu.y) * (1.f / (1.f + __expf(-l1)));
                const __half2 ugh = __floats2half2_rn(ug0, ug1);
                *(__half2*)(g_ugh + off) = ugh;
                const float ur0 = __half2float(ugh.x);
                const float ur1 = __half2float(ugh.y);
                Q0 = fmaf(Q0, a8_0, ur0);
                Q1 = fmaf(Q1, a8_1, ur1);
                csum[j][0] += ug0;
                csum[j][1] += ug1;
            }
        }
        float p0 = 1.f, p1 = 1.f;
        for (int k = 0; k < 7 - g; k++) { p0 *= aa0; p1 *= aa1; }
        if (warp_m == 0) {
            float a64_0 = a8_0 * a8_0; a64_0 *= a64_0; a64_0 *= a64_0;  // aa^64
            float a64_1 = a8_1 * a8_1; a64_1 *= a64_1; a64_1 *= a64_1;
            p0 *= a64_0; p1 *= a64_1;
        }
        float P0 = Q0 * p0 * s_bb[col];
        float P1 = Q1 * p1 * s_bb[col + 1];
#pragma unroll
        for (int mask = 16; mask >= 4; mask >>= 1) {
            P0 += __shfl_xor_sync(0xffffffffu, P0, mask);
            P1 += __shfl_xor_sync(0xffffffffu, P1, mask);
        }
        if (g == 0) {
            s_car[warp_m][col] = P0;
            s_car[warp_m][col + 1] = P1;
        }
    }
#pragma unroll
    for (int j = 0; j < 4; j++) {
#pragma unroll
        for (int mask = 16; mask >= 4; mask >>= 1) {
            csum[j][0] += __shfl_xor_sync(0xffffffffu, csum[j][0], mask);
            csum[j][1] += __shfl_xor_sync(0xffffffffu, csum[j][1], mask);
        }
    }
    if (g == 0) {
#pragma unroll
        for (int j = 0; j < 4; j++) {
            s_red[warp_m][warp_n * 32 + j * 8 + 2 * t] = csum[j][0];
            s_red[warp_m][warp_n * 32 + j * 8 + 2 * t + 1] = csum[j][1];
        }
    }
    __syncthreads();
    if (tid < BN) {
        g_partials[(size_t)blockIdx.y * Ddim + n0 + tid] =
            s_red[0][tid] + s_red[1][tid];
        g_carry[(size_t)blockIdx.y * Ddim + n0 + tid] =
            s_car[0][tid] + s_car[1][tid];
    }
}

// ==== Kernel 2: g_rp[(b*8+slice)][r] partial rank-4 sums (64 blocks) =======
__global__ __launch_bounds__(256)
void rvec_part(const float* __restrict__ dlru) {   // [D, 4]
    const int blk = blockIdx.x;      // 0..63
    const int b = blk >> 3;
    const int slice = blk & 7;
    const int tid = threadIdx.x;     // 256
    __shared__ float s_m[8][4];
    const int e = slice * 256 + tid;
    float s = 0.f;
#pragma unroll
    for (int i = 0; i < 16; i++)
        s += g_partials[(size_t)(b * 16 + i) * Ddim + e];
    const float mean = s * (1.0f / Tdim);
    const float4 w = ((const float4*)dlru)[e];
    float a0 = mean * w.x, a1 = mean * w.y, a2 = mean * w.z, a3 = mean * w.w;
#pragma unroll
    for (int mask = 16; mask >= 1; mask >>= 1) {
        a0 += __shfl_xor_sync(0xffffffffu, a0, mask);
        a1 += __shfl_xor_sync(0xffffffffu, a1, mask);
        a2 += __shfl_xor_sync(0xffffffffu, a2, mask);
        a3 += __shfl_xor_sync(0xffffffffu, a3, mask);
    }
    const int wid = tid >> 5;
    if ((tid & 31) == 0) {
        s_m[wid][0] = a0; s_m[wid][1] = a1; s_m[wid][2] = a2; s_m[wid][3] = a3;
    }
    __syncthreads();
    if (tid < 4) {
        float r = 0.f;
#pragma unroll
        for (int i = 0; i < 8; i++) r += s_m[i][tid];
        g_rp[blk * 4 + tid] = r;
    }
}

// ==== Kernel 3: chunk replay + output, 4 channels per thread ===============
__global__ __launch_bounds__(256)
void scan_p3(const float* __restrict__ av,
             const float* __restrict__ bv,
             const float* __restrict__ cv,
             const float* __restrict__ dvec,
             const float* __restrict__ dlrv,   // [4, D]
             float* __restrict__ Y) {
    const int qid = blockIdx.x * 256 + threadIdx.x;    // 0 .. NCH*CCH/4-1
    const int cb = qid * 4;                             // first of 4 channels
    const int dd = cb & (Ddim - 1);
    const int rest = cb >> 11;                          // b*CCH + chunk
    const int b = rest >> 4;
    const int chunk = rest & (CCH - 1);

    float aa[4], bb[4], cc[4], de[4], s[4];
    {
        const float4 a4 = *(const float4*)(av + dd);
        const float4 b4 = *(const float4*)(bv + dd);
        const float4 c4 = *(const float4*)(cv + dd);
        const float4 d4 = *(const float4*)(dvec + dd);
        aa[0] = tanhf(a4.x); aa[1] = tanhf(a4.y);
        aa[2] = tanhf(a4.z); aa[3] = tanhf(a4.w);
        bb[0] = b4.x; bb[1] = b4.y; bb[2] = b4.z; bb[3] = b4.w;
        cc[0] = c4.x; cc[1] = c4.y; cc[2] = c4.z; cc[3] = c4.w;

        float r0 = 0.f, r1 = 0.f, r2 = 0.f, r3 = 0.f;
#pragma unroll
        for (int sl = 0; sl < 8; sl++) {
            const float4 rp = ((const float4*)g_rp)[b * 8 + sl];
            r0 += rp.x; r1 += rp.y; r2 += rp.z; r3 += rp.w;
        }
        const float4 v0 = *(const float4*)(dlrv + dd);
        const float4 v1 = *(const float4*)(dlrv + Ddim + dd);
        const float4 v2 = *(const float4*)(dlrv + 2 * Ddim + dd);
        const float4 v3 = *(const float4*)(dlrv + 3 * Ddim + dd);
        de[0] = d4.x + 0.25f * (r0 * v0.x + r1 * v1.x + r2 * v2.x + r3 * v3.x);
        de[1] = d4.y + 0.25f * (r0 * v0.y + r1 * v1.y + r2 * v2.y + r3 * v3.y);
        de[2] = d4.z + 0.25f * (r0 * v0.z + r1 * v1.z + r2 * v2.z + r3 * v3.z);
        de[3] = d4.w + 0.25f * (r0 * v0.w + r1 * v1.w + r2 * v2.w + r3 * v3.w);
    }

    // entry state: same combine order as the old p2 (bitwise identical)
    float aL[4];
#pragma unroll
    for (int i = 0; i < 4; i++) {
        float x = aa[i];
#pragma unroll
        for (int k = 0; k < 7; k++) x *= x;             // aa^128
        aL[i] = x;
        s[i] = 0.f;
    }
#pragma unroll 1
    for (int j = 0; j < chunk; j++) {
        const float4 c4 = *(const float4*)(g_carry + (b * CCH + j) * Ddim + dd);
        s[0] = fmaf(aL[0], s[0], c4.x);
        s[1] = fmaf(aL[1], s[1], c4.y);
        s[2] = fmaf(aL[2], s[2], c4.z);
        s[3] = fmaf(aL[3], s[3], c4.w);
    }

    const __half* p = g_ugh + (size_t)rest * LCH * Ddim + dd;
    float* q = Y + (size_t)rest * LCH * Ddim + dd;
#pragma unroll 1
    for (int t0 = 0; t0 < LCH; t0 += 8) {
        uint2 x[8];
#pragma unroll
        for (int j = 0; j < 8; j++)
            x[j] = __ldcs((const uint2*)(p + (size_t)(t0 + j) * Ddim));
#pragma unroll
        for (int j = 0; j < 8; j++) {
            const __half2 lo = *(const __half2*)&x[j].x;
            const __half2 hi = *(const __half2*)&x[j].y;
            const float xf0 = __half2float(lo.x);
            const float xf1 = __half2float(lo.y);
            const float xf2 = __half2float(hi.x);
            const float xf3 = __half2float(hi.y);
            s[0] = fmaf(aa[0], s[0], bb[0] * xf0);
            s[1] = fmaf(aa[1], s[1], bb[1] * xf1);
            s[2] = fmaf(aa[2], s[2], bb[2] * xf2);
            s[3] = fmaf(aa[3], s[3], bb[3] * xf3);
            float4 out;
            out.x = fmaf(cc[0], s[0], de[0] * xf0);
            out.y = fmaf(cc[1], s[1], de[1] * xf1);
            out.z = fmaf(cc[2], s[2], de[2] * xf2);
            out.w = fmaf(cc[3], s[3], de[3] * xf3);
            __stcs((float4*)(q + (size_t)(t0 + j) * Ddim), out);
        }
    }
}

extern "C" void kernel_launch(void* const* d_in, const int* in_sizes, int n_in,
                              void* d_out, int out_size) {
    const float* U    = (const float*)d_in[0];  // [B,T,D]
    const float* av   = (const float*)d_in[1];  // [D]
    const float* bv   = (const float*)d_in[2];  // [D]
    const float* cv   = (const float*)d_in[3];  // [D]
    const float* dv   = (const float*)d_in[4];  // [D]
    const float* gw   = (const float*)d_in[5];  // [D,D]
    const float* gbp  = (const float*)d_in[6];  // [D]
    const float* dlru = (const float*)d_in[7];  // [D,4]
    const float* dlrv = (const float*)d_in[8];  // [4,D]
    float* Y = (float*)d_out;

    __half* uh_p; cudaGetSymbolAddress((void**)&uh_p, g_uh);
    __half* wh_p; cudaGetSymbolAddress((void**)&wh_p, g_wh);

    conv_both<<<(unsigned)((NU4 + NW4) / 256), 256>>>(U, gw, uh_p, wh_p);

    cudaFuncSetAttribute(gemm_gate_mma,
                         cudaFuncAttributeMaxDynamicSharedMemorySize, DYN_BYTES);
    gemm_gate_mma<<<dim3(NTILES, MTILES), 256, DYN_BYTES>>>(gbp, av, bv);
    rvec_part<<<64, 256>>>(dlru);
    scan_p3<<<(NCH * CCH / 4) / 256, 256>>>(av, bv, cv, dv, dlrv, Y);
}